// round 14
// baseline (speedup 1.0000x reference)
#include <cuda_runtime.h>
#include <cuda_bf16.h>
#include <cstddef>

#define Bn 2
#define Cc 64
#define Hh 256
#define Ww 256
#define HW (Hh*Ww)

typedef unsigned long long ull;

__device__ float g_A[(size_t)Bn*Cc*HW];
__device__ float g_B[(size_t)Bn*Cc*HW];
__device__ ull   g_WP[6*64*9*32];

__device__ __forceinline__ ull pack2(float lo, float hi) {
    ull r; asm("mov.b64 %0, {%1, %2};" : "=l"(r) : "f"(lo), "f"(hi)); return r;
}
__device__ __forceinline__ ull dup2(float v) {
    ull r; asm("mov.b64 %0, {%1, %1};" : "=l"(r) : "f"(v)); return r;
}
__device__ __forceinline__ void unpack2(ull v, float& lo, float& hi) {
    asm("mov.b64 {%0, %1}, %2;" : "=f"(lo), "=f"(hi) : "l"(v));
}
__device__ __forceinline__ ull ffma2(ull a, ull b, ull c) {
    ull d; asm("fma.rn.f32x2 %0, %1, %2, %3;" : "=l"(d) : "l"(a), "l"(b), "l"(c)); return d;
}
__device__ __forceinline__ ull add2(ull a, ull b) {
    ull d; asm("add.rn.f32x2 %0, %1, %2;" : "=l"(d) : "l"(a), "l"(b)); return d;
}
__device__ __forceinline__ unsigned smem_u32(const void* p) {
    unsigned a;
    asm("{ .reg .u64 t; cvta.to.shared.u64 t, %1; cvt.u32.u64 %0, t; }" : "=r"(a) : "l"(p));
    return a;
}
__device__ __forceinline__ void cp_async4(unsigned dst, const void* src, int sz) {
    asm volatile("cp.async.ca.shared.global [%0], [%1], 4, %2;" :: "r"(dst), "l"(src), "r"(sz) : "memory");
}
__device__ __forceinline__ void cp_async16(unsigned dst, const void* src) {
    asm volatile("cp.async.cg.shared.global [%0], [%1], 16;" :: "r"(dst), "l"(src) : "memory");
}
__device__ __forceinline__ void cp_commit() { asm volatile("cp.async.commit_group;" ::: "memory"); }
template<int N> __device__ __forceinline__ void cp_wait() {
    asm volatile("cp.async.wait_group %0;" :: "n"(N) : "memory");
}

// ---- one-shot weight packer: wp[layer][ci][k][pr] ----
__global__ void pack_w_k(const float* __restrict__ w0, const float* __restrict__ w1,
                         const float* __restrict__ w2, const float* __restrict__ w3,
                         const float* __restrict__ w4, const float* __restrict__ w5,
                         ull* __restrict__ wp)
{
    int idx = blockIdx.x*256 + threadIdx.x;
    if (idx >= 110592) return;
    int layer = idx / 18432; int r = idx - layer*18432;
    int ci  = r / 288;       r -= ci*288;
    int k   = r / 32;        int pr = r - k*32;
    const float* w = (layer==0)?w0:(layer==1)?w1:(layer==2)?w2:
                     (layer==3)?w3:(layer==4)?w4:w5;
    int co0 = pr*2;
    wp[idx] = pack2(w[(co0*Cc + ci)*9 + k], w[((co0+1)*Cc + ci)*9 + k]);
}

// ---- 1x1 fuse conv: 16 out-ch per block, 3 CTAs/SM ----
// grid (HW/512, 4, B); block 256. Thread: 2 px x 8 co-pairs.
__global__ void __launch_bounds__(256, 3)
fuse1x1_k(const float* __restrict__ img, const float* __restrict__ gui,
          const float* __restrict__ w, const float* __restrict__ bias,
          const float* __restrict__ a_ptr, float* __restrict__ out)
{
    __shared__ ull s_wp[8*128];
    const int tid = threadIdx.x;
    const int cog = blockIdx.y;          // 0..3 -> out-ch base cog*16
    const int b = blockIdx.z;
    for (int e = tid; e < 8*128; e += 256) {
        int jp = e >> 7, ci = e & 127;
        int co0 = cog*16 + 2*jp;
        s_wp[e] = pack2(w[co0*128 + ci], w[(co0+1)*128 + ci]);
    }
    __syncthreads();
    const int p0 = blockIdx.x*512 + tid;
    ull acc[8][2];
#pragma unroll
    for (int jp = 0; jp < 8; ++jp) {
        int co0 = cog*16 + 2*jp;
        ull bv = pack2(bias[co0], bias[co0+1]);
        acc[jp][0] = bv; acc[jp][1] = bv;
    }
    const float* i0 = img + (size_t)b*Cc*HW + p0;
    const float* i1 = gui + (size_t)b*Cc*HW + p0;
#pragma unroll 2
    for (int ci = 0; ci < 64; ++ci) {
        const float* ic = i0 + (size_t)ci*HW;
        ull vp0 = dup2(ic[0]), vp1 = dup2(ic[256]);
#pragma unroll
        for (int jp = 0; jp < 8; ++jp) {
            ull wv = s_wp[jp*128 + ci];
            acc[jp][0] = ffma2(vp0, wv, acc[jp][0]);
            acc[jp][1] = ffma2(vp1, wv, acc[jp][1]);
        }
    }
#pragma unroll 2
    for (int ci = 0; ci < 64; ++ci) {
        const float* ic = i1 + (size_t)ci*HW;
        ull vp0 = dup2(ic[0]), vp1 = dup2(ic[256]);
#pragma unroll
        for (int jp = 0; jp < 8; ++jp) {
            ull wv = s_wp[jp*128 + 64 + ci];
            acc[jp][0] = ffma2(vp0, wv, acc[jp][0]);
            acc[jp][1] = ffma2(vp1, wv, acc[jp][1]);
        }
    }
    const float a = a_ptr[0];
#pragma unroll
    for (int jp = 0; jp < 8; ++jp) {
        int co0 = cog*16 + 2*jp;
        float* o0 = out + ((size_t)b*Cc + co0)*HW + p0;
        float* o1 = o0 + HW;
#pragma unroll
        for (int q = 0; q < 2; ++q) {
            float lo, hi; unpack2(acc[jp][q], lo, hi);
            lo = (lo >= 0.f) ? lo : a*lo;
            hi = (hi >= 0.f) ? hi : a*hi;
            o0[q*256] = lo; o1[q*256] = hi;
        }
    }
}

// ---- direct 3x3 conv: 3 CTAs/SM, double-buffered, 32 co per CTA ----
#define SIN_F   2800
#define SW_U    1152
#define SIN_BYTES (SIN_F*4)
#define SW_BYTES  (SW_U*8)
#define CONV_SMEM (2*(SIN_BYTES + SW_BYTES))   // 40832

template<bool PRELU, bool RESID>
__global__ void __launch_bounds__(256, 3)
conv3x3_k(const float* __restrict__ in,
          const ull*   __restrict__ wp,    // [ci][k][32 pairs]
          const float* __restrict__ bias,
          const float* __restrict__ a_ptr,
          const float* __restrict__ resid,
          float* __restrict__ out)
{
    extern __shared__ __align__(16) char dyn_smem[];
    float* sin_f = (float*)dyn_smem;
    ull*   sw_u  = (ull*)(dyn_smem + 2*SIN_BYTES);
    const unsigned sin_base = smem_u32(sin_f);
    const unsigned sw_base  = smem_u32(sw_u);

    const int tid = threadIdx.x;
    const int x0  = blockIdx.x * 32;
    const int y0  = blockIdx.y * 8;
    const int cog = blockIdx.z & 1;
    const int b   = blockIdx.z >> 1;
    const int wg  = tid >> 5;
    const int lane = tid & 31;
    const int rp  = lane >> 3;
    const int xs  = (lane & 7) * 4;
    const int co0 = cog*32 + wg*4;

    ull acc[2][2][4];
#pragma unroll
    for (int j = 0; j < 2; ++j) {
        ull bv = pack2(bias[co0 + 2*j], bias[co0 + 2*j + 1]);
#pragma unroll
        for (int L = 0; L < 2; ++L)
#pragma unroll
            for (int px = 0; px < 4; ++px) acc[j][L][px] = bv;
    }

    const float* inb = in + (size_t)b*Cc*HW;

    // hoisted halo staging offsets
    unsigned hdst[11]; int hsrc[11]; unsigned hmask = 0;
#pragma unroll
    for (int q = 0; q < 11; ++q) {
        int e = tid + q*256;
        int cc  = e / 340;
        int idx = e - cc*340;
        int r   = idx / 34;
        int c2  = idx - r*34;
        int gy = y0 - 1 + r, gx = x0 - 1 + c2;
        bool ok = (e < 2720) &&
                  ((unsigned)gy < (unsigned)Hh) && ((unsigned)gx < (unsigned)Ww);
        hdst[q] = (unsigned)(cc*350 + r*35 + c2) * 4u;
        hsrc[q] = ok ? (cc*HW + gy*Ww + gx) : 0;
        if (ok) hmask |= 1u << q;
    }

    // hoisted weight staging offsets (e < 576; e -> ci=e/72, r2=e%72)
    unsigned wdst[3]; int wsrc[3];
#pragma unroll
    for (int q = 0; q < 3; ++q) {
        int e = tid + q*256;
        if (e >= 576) e = 0;       // lanes beyond 576 are predicated off at issue
        int ci = e / 72;
        int r2 = e - ci*72;
        wsrc[q] = ci*288 + (r2 >> 3)*32 + cog*16 + (r2 & 7)*2;
        wdst[q] = (unsigned)((ci*72 + r2)*16);
    }

    auto issue = [&](int bi, int cb) {
        const float* srcb = inb + (size_t)cb*HW;
        unsigned sbase = sin_base + bi*SIN_BYTES;
#pragma unroll
        for (int q = 0; q < 11; ++q) {
            if (q < 10 || tid < 160) {
                int ok4 = (hmask >> q) & 1;
                cp_async4(sbase + hdst[q], srcb + hsrc[q], ok4 << 2);
            }
        }
        const ull* wb = wp + (size_t)cb*288;
        unsigned wbase = sw_base + bi*SW_BYTES;
#pragma unroll
        for (int q = 0; q < 3; ++q) {
            if (q < 2 || tid < 64) {
                cp_async16(wbase + wdst[q], wb + wsrc[q]);
            }
        }
        cp_commit();
    };

    issue(0, 0);

    for (int s = 0; s < 8; ++s) {
        cp_wait<0>();
        __syncthreads();
        if (s < 7) issue((s + 1) & 1, (s + 1) * 8);

        const int bi = s & 1;
        const float* sif = sin_f + bi*SIN_F;
        const ull*   swu = sw_u  + bi*SW_U;
#pragma unroll
        for (int cc = 0; cc < 8; ++cc) {
#pragma unroll
            for (int r_in = 0; r_in < 4; ++r_in) {
                const int h = 2*rp + r_in;
                ull tp[6];
#pragma unroll
                for (int c = 0; c < 6; ++c) {
                    float t = sif[cc*350 + h*35 + xs + c];
                    tp[c] = dup2(t);
                }
#pragma unroll
                for (int L = 0; L < 2; ++L) {
                    if (r_in - L < 0 || r_in - L > 2) continue;
                    const int dy = r_in - L;
#pragma unroll
                    for (int dx = 0; dx < 3; ++dx) {
                        const int k = dy*3 + dx;
                        ulonglong2 w01 = *(const ulonglong2*)&swu[(cc*9 + k)*16 + wg*2];
#pragma unroll
                        for (int px = 0; px < 4; ++px) {
                            ull a = tp[px + dx];
                            acc[0][L][px] = ffma2(a, w01.x, acc[0][L][px]);
                            acc[1][L][px] = ffma2(a, w01.y, acc[1][L][px]);
                        }
                    }
                }
            }
        }
    }

    float a = 0.f;
    if (PRELU) a = a_ptr[0];
    const int x = x0 + xs;
#pragma unroll
    for (int j = 0; j < 2; ++j) {
#pragma unroll
        for (int L = 0; L < 2; ++L) {
            const int y = y0 + 2*rp + L;
            float v0[4], v1[4];
#pragma unroll
            for (int px = 0; px < 4; ++px) {
                unpack2(acc[j][L][px], v0[px], v1[px]);
                if (PRELU) {
                    v0[px] = (v0[px] >= 0.f) ? v0[px] : a*v0[px];
                    v1[px] = (v1[px] >= 0.f) ? v1[px] : a*v1[px];
                }
            }
            size_t o0 = ((size_t)(b*Cc + co0 + 2*j)*Hh + y)*Ww + x;
            size_t o1 = o0 + (size_t)HW;
            float4 a0 = make_float4(v0[0], v0[1], v0[2], v0[3]);
            float4 b0 = make_float4(v1[0], v1[1], v1[2], v1[3]);
            if (RESID) {
                float4 r0 = *(const float4*)(resid + o0);
                float4 r1 = *(const float4*)(resid + o1);
                a0.x += r0.x; a0.y += r0.y; a0.z += r0.z; a0.w += r0.w;
                b0.x += r1.x; b0.y += r1.y; b0.z += r1.z; b0.w += r1.w;
            }
            *(float4*)(out + o0) = a0;
            *(float4*)(out + o1) = b0;
        }
    }
}

// ---- fused kg5 + dynamic JBF (unchanged from R12/R13) ----
#define KGJ_SMEM (288*64*4 + 288*4)

__global__ void __launch_bounds__(256, 2)
kgjbf_k(const float* __restrict__ y4, const float* __restrict__ w5,
        const float* __restrict__ b5, const float* __restrict__ img,
        float* __restrict__ out)
{
    extern __shared__ float smem[];
    float* s_w5 = smem;
    float* s_b5 = smem + 288*64;
    const int tid = threadIdx.x;
    const int ci0 = blockIdx.y*32;
    const int b = blockIdx.z;
    const int p = blockIdx.x * 256 + tid;
    const int y = p >> 8;
    const int x = p & 255;
    {
        float4* dst = (float4*)s_w5;
        for (int e = tid; e < 288*16; e += 256) {
            int row = e >> 4, q = e & 15;
            int f = ((row >> 5) << 6) + ci0 + (row & 31);
            dst[e] = ((const float4*)(w5 + (size_t)f*64))[q];
        }
        for (int e = tid; e < 288; e += 256)
            s_b5[e] = b5[((e >> 5) << 6) + ci0 + (e & 31)];
    }
    __syncthreads();
    ull yp[32];
    {
        const float* yb = y4 + (size_t)b*Cc*HW + p;
#pragma unroll
        for (int c2 = 0; c2 < 32; ++c2)
            yp[c2] = pack2(yb[(size_t)(2*c2)*HW], yb[(size_t)(2*c2+1)*HW]);
    }
    const float* ib = img + (size_t)b*Cc*HW;
    float* ob = out + ((size_t)b*Cc + ci0)*HW + p;

    int off[9]; unsigned okm = 0;
#pragma unroll
    for (int t = 0; t < 9; ++t) {
        int dy = t/3 - 1, dx = t - (t/3)*3 - 1;
        int yy = y + dy, xx = x + dx;
        off[t] = yy*Ww + xx;
        if ((unsigned)yy < (unsigned)Hh && (unsigned)xx < (unsigned)Ww) okm |= 1u << t;
    }
    const int tap00 = ci0 % 9;

    for (int j = 0; j < 32; ++j) {
        const int ci = ci0 + j;
        int tap0 = (tap00 + j) % 9;
        float acc = 0.f;
#pragma unroll
        for (int t = 0; t < 9; ++t) {
            int kk = t - tap0; kk += (kk < 0) ? 9 : 0;
            const int row = kk*32 + j;
            const ulonglong2* wrow = (const ulonglong2*)(s_w5 + row*64);
            ull p0 = 0ULL, p1 = 0ULL, p2 = 0ULL, p3 = 0ULL;
#pragma unroll
            for (int c4 = 0; c4 < 16; c4 += 4) {
                ulonglong2 wv0 = wrow[c4  ];
                ulonglong2 wv1 = wrow[c4+1];
                ulonglong2 wv2 = wrow[c4+2];
                ulonglong2 wv3 = wrow[c4+3];
                p0 = ffma2(yp[2*c4  ], wv0.x, p0);
                p1 = ffma2(yp[2*c4+1], wv0.y, p1);
                p2 = ffma2(yp[2*c4+2], wv1.x, p2);
                p3 = ffma2(yp[2*c4+3], wv1.y, p3);
                p0 = ffma2(yp[2*c4+4], wv2.x, p0);
                p1 = ffma2(yp[2*c4+5], wv2.y, p1);
                p2 = ffma2(yp[2*c4+6], wv3.x, p2);
                p3 = ffma2(yp[2*c4+7], wv3.y, p3);
            }
            p0 = add2(p0, p1); p2 = add2(p2, p3); p0 = add2(p0, p2);
            float lo, hi; unpack2(p0, lo, hi);
            float bik = lo + hi + s_b5[row];
            unsigned ch = (unsigned)(64*kk + ci - t) * 0x38E38E39u;
            float iv = 0.f;
            if ((okm >> t) & 1) iv = ib[(size_t)ch*HW + off[t]];
            acc = fmaf(bik, iv, acc);
        }
        ob[(size_t)j*HW] = acc;
    }
}

// ---------------------------------------------------------------------------
extern "C" void kernel_launch(void* const* d_in, const int* in_sizes, int n_in,
                              void* d_out, int out_size)
{
    const float* image   = (const float*)d_in[0];
    const float* guidance= (const float*)d_in[1];
    const float* tensor_w= (const float*)d_in[2];
    const float* tensor_b= (const float*)d_in[3];
    const float* a_jbf   = (const float*)d_in[4];
    const float* kg_w1   = (const float*)d_in[5];
    const float* kg_b1   = (const float*)d_in[6];
    const float* kg_w2   = (const float*)d_in[7];
    const float* kg_b2   = (const float*)d_in[8];
    const float* kg_w3   = (const float*)d_in[9];
    const float* kg_b3   = (const float*)d_in[10];
    const float* kg_w4   = (const float*)d_in[11];
    const float* kg_b4   = (const float*)d_in[12];
    const float* kg_w5   = (const float*)d_in[13];
    const float* kg_b5   = (const float*)d_in[14];
    const float* a_kg    = (const float*)d_in[15];
    const float* jbf_w1  = (const float*)d_in[16];
    const float* jbf_b1  = (const float*)d_in[17];
    const float* jbf_w2  = (const float*)d_in[18];
    const float* jbf_b2  = (const float*)d_in[19];
    float* out = (float*)d_out;

    float *A, *Bb;
    ull* WP;
    cudaGetSymbolAddress((void**)&A,  g_A);
    cudaGetSymbolAddress((void**)&Bb, g_B);
    cudaGetSymbolAddress((void**)&WP, g_WP);

    static bool attr_set = false;
    if (!attr_set) {
        cudaFuncSetAttribute(kgjbf_k, cudaFuncAttributeMaxDynamicSharedMemorySize, KGJ_SMEM);
        cudaFuncSetAttribute(conv3x3_k<true,false>,
                             cudaFuncAttributeMaxDynamicSharedMemorySize, CONV_SMEM);
        cudaFuncSetAttribute(conv3x3_k<false,true>,
                             cudaFuncAttributeMaxDynamicSharedMemorySize, CONV_SMEM);
        attr_set = true;
    }

    dim3 blk(256);
    dim3 gf(HW/512, 4, Bn);
    dim3 g3(Ww/32, Hh/8, 2*Bn);
    dim3 gj(HW/256, 2, Bn);

    pack_w_k<<<(110592 + 255)/256, blk>>>(kg_w1, kg_w2, kg_w3, kg_w4, jbf_w1, jbf_w2, WP);

    fuse1x1_k<<<gf, blk>>>(image, guidance, tensor_w, tensor_b, a_jbf, A);
    conv3x3_k<true,false><<<g3, blk, CONV_SMEM>>>(A,  WP + 0*18432, kg_b1, a_kg, nullptr, Bb);
    conv3x3_k<true,false><<<g3, blk, CONV_SMEM>>>(Bb, WP + 1*18432, kg_b2, a_kg, nullptr, A);
    conv3x3_k<true,false><<<g3, blk, CONV_SMEM>>>(A,  WP + 2*18432, kg_b3, a_kg, nullptr, Bb);
    conv3x3_k<true,false><<<g3, blk, CONV_SMEM>>>(Bb, WP + 3*18432, kg_b4, a_kg, nullptr, A);
    kgjbf_k<<<gj, blk, KGJ_SMEM>>>(A, kg_w5, kg_b5, image, Bb);
    conv3x3_k<true,false><<<g3, blk, CONV_SMEM>>>(Bb, WP + 4*18432, jbf_b1, a_jbf, nullptr, A);
    conv3x3_k<false,true><<<g3, blk, CONV_SMEM>>>(A,  WP + 5*18432, jbf_b2, nullptr, image, out);
}